// round 5
// baseline (speedup 1.0000x reference)
#include <cuda_runtime.h>
#include <cstdint>

#define B_  32
#define S_  2048
#define C_  1024
#define G_  16
#define K_  256

__device__ float         g_norms[B_ * G_ * S_];   // (B*g, S) row-major
__device__ unsigned char g_mask [B_ * G_ * S_];

// ---------------------------------------------------------------------------
// K1: sum-of-squares per (b,s,group). 8 bs-rows per block, 256 threads,
// front-batched streaming loads (MLP=8).  [R3-proven shape]
// ---------------------------------------------------------------------------
__global__ __launch_bounds__(256) void k_norms(const float* __restrict__ x) {
    const int base_bs = blockIdx.x << 3;
    const int t = threadIdx.x;
    float4 v[8];
    #pragma unroll
    for (int r = 0; r < 8; r++)
        v[r] = __ldcs(reinterpret_cast<const float4*>(
                          x + (size_t)(base_bs + r) * C_) + t);
    #pragma unroll
    for (int r = 0; r < 8; r++) {
        float ss = v[r].x * v[r].x + v[r].y * v[r].y
                 + v[r].z * v[r].z + v[r].w * v[r].w;
        #pragma unroll
        for (int off = 8; off > 0; off >>= 1)
            ss += __shfl_down_sync(0xffffffffu, ss, off, 16);
        if ((t & 15) == 0) {
            const int bs = base_bs + r;
            const int b  = bs >> 11;
            const int s  = bs & (S_ - 1);
            g_norms[((b << 4) + (t >> 4)) * S_ + s] = ss;
        }
    }
}

// ---------------------------------------------------------------------------
// K2: exact Kth-largest per row via 4-pass radix select on the monotone uint
// encoding (values >= 0). Exact-K mask with tie fill. 512 blocks x 256 thr.
// ---------------------------------------------------------------------------
__global__ __launch_bounds__(256) void k_select() {
    __shared__ unsigned int vals[S_];
    __shared__ int hist[256];
    __shared__ int sh_k;
    __shared__ unsigned int sh_prefix;
    __shared__ int n_gt, eq_cnt;

    const int row = blockIdx.x;
    const int tid = threadIdx.x;
    const float* nr = g_norms + (size_t)row * S_;

    #pragma unroll
    for (int i = tid; i < S_; i += 256)
        vals[i] = __float_as_uint(nr[i]);
    if (tid == 0) { sh_k = K_; sh_prefix = 0u; n_gt = 0; eq_cnt = 0; }
    hist[tid] = 0;
    __syncthreads();

    int k = K_;
    unsigned int prefix = 0u;
    #pragma unroll
    for (int shift = 24; shift >= 0; shift -= 8) {
        if (shift == 24) {
            #pragma unroll
            for (int i = tid; i < S_; i += 256)
                atomicAdd(&hist[vals[i] >> 24], 1);
        } else {
            const unsigned int pmask = 0xFFFFFFFFu << (shift + 8);
            #pragma unroll
            for (int i = tid; i < S_; i += 256) {
                const unsigned int u = vals[i];
                if ((u & pmask) == prefix)
                    atomicAdd(&hist[(u >> shift) & 255], 1);
            }
        }
        __syncthreads();

        if (tid < 32) {
            const int binbase = 255 - tid * 8;  // lane 0 owns top bins
            int c = 0;
            #pragma unroll
            for (int j = 0; j < 8; j++) c += hist[binbase - j];
            int inc = c;
            #pragma unroll
            for (int off = 1; off < 32; off <<= 1) {
                const int nth = __shfl_up_sync(0xffffffffu, inc, off);
                if (tid >= off) inc += nth;
            }
            const int pre = inc - c;
            const bool hit = (pre < k) && (pre + c >= k);
            const unsigned int bal = __ballot_sync(0xffffffffu, hit);
            if (tid == (__ffs(bal) - 1)) {
                int cum = pre;
                #pragma unroll
                for (int j = 0; j < 8; j++) {
                    const int h = hist[binbase - j];
                    if (cum + h >= k) {
                        sh_k = k - cum;
                        sh_prefix = prefix |
                            ((unsigned int)(binbase - j) << shift);
                        break;
                    }
                    cum += h;
                }
            }
        }
        __syncthreads();
        k = sh_k;
        prefix = sh_prefix;
        hist[tid] = 0;
        __syncthreads();
    }

    const float thr = __uint_as_float(prefix);  // exact Kth largest

    int loc = 0;
    #pragma unroll
    for (int i = tid; i < S_; i += 256)
        loc += (__uint_as_float(vals[i]) > thr) ? 1 : 0;
    #pragma unroll
    for (int off = 16; off > 0; off >>= 1)
        loc += __shfl_down_sync(0xffffffffu, loc, off);
    if ((tid & 31) == 0) atomicAdd(&n_gt, loc);
    __syncthreads();

    const int ngt = n_gt;
    unsigned char* mrow = g_mask + (size_t)row * S_;
    #pragma unroll
    for (int i = tid; i < S_; i += 256) {
        const float v = __uint_as_float(vals[i]);
        unsigned char m = 0;
        if (v > thr) m = 1;
        else if (v == thr) {
            const int p = atomicAdd(&eq_cnt, 1);
            m = (ngt + p < K_) ? 1 : 0;
        }
        mrow[i] = m;
    }
}

// ---------------------------------------------------------------------------
// K3: apply mask, latency-decoupled. Zero-stores for all 8 rows are issued
// FIRST with no dependencies (store pipe starts at cycle 0). Then one uint64
// mask load covers all 8 rows; only selected rows (~12.5%) are re-loaded and
// re-stored. The overwrite hits the just-written line in L2, so the extra
// DRAM traffic is small while the dependent chain shrinks to 12.5% of writes.
// ---------------------------------------------------------------------------
__global__ __launch_bounds__(256) void k_apply(const float* __restrict__ x,
                                               float* __restrict__ out) {
    const int base_bs = blockIdx.x << 3;   // aligned to 8; same b for all 8
    const int t  = threadIdx.x;
    const int g  = t >> 4;
    const int b  = base_bs >> 11;
    const int s0 = base_bs & (S_ - 1);

    // Eager zero fill — no dependency on the mask or x.
    const float4 z = make_float4(0.f, 0.f, 0.f, 0.f);
    #pragma unroll
    for (int r = 0; r < 8; r++)
        reinterpret_cast<float4*>(out + (size_t)(base_bs + r) * C_)[t] = z;

    const unsigned long long mbits =
        *reinterpret_cast<const unsigned long long*>(
            &g_mask[(size_t)((b << 4) + g) * S_ + s0]);

    if (mbits == 0ull) return;

    float4 v[8];
    #pragma unroll
    for (int r = 0; r < 8; r++) {
        if ((mbits >> (r << 3)) & 0xFFull)
            v[r] = __ldcs(reinterpret_cast<const float4*>(
                              x + (size_t)(base_bs + r) * C_) + t);
    }
    #pragma unroll
    for (int r = 0; r < 8; r++) {
        if ((mbits >> (r << 3)) & 0xFFull)
            reinterpret_cast<float4*>(
                out + (size_t)(base_bs + r) * C_)[t] = v[r];
    }
}

extern "C" void kernel_launch(void* const* d_in, const int* in_sizes, int n_in,
                              void* d_out, int out_size) {
    const float* x = (const float*)d_in[0];
    float* out = (float*)d_out;
    k_norms <<<(B_ * S_) / 8, 256>>>(x);
    k_select<<<B_ * G_, 256>>>();
    k_apply <<<(B_ * S_) / 8, 256>>>(x, out);
}

// round 6
// speedup vs baseline: 1.0196x; 1.0196x over previous
#include <cuda_runtime.h>
#include <cstdint>

#define B_  32
#define S_  2048
#define C_  1024
#define G_  16
#define K_  256

__device__ float         g_norms[B_ * G_ * S_];   // (B*g, S) row-major
__device__ unsigned char g_mask [B_ * G_ * S_];

// ---------------------------------------------------------------------------
// K1 (fused): sum-of-squares per (b,s,group) AND zero-fill of out.
// 8 bs-rows per block, 256 threads. The 8 loads and 8 zero-stores are
// mutually independent -> read and write streams overlap in one kernel.
// ---------------------------------------------------------------------------
__global__ __launch_bounds__(256) void k_norms_zero(const float* __restrict__ x,
                                                    float* __restrict__ out) {
    const int base_bs = blockIdx.x << 3;
    const int t = threadIdx.x;

    float4 v[8];
    #pragma unroll
    for (int r = 0; r < 8; r++)
        v[r] = __ldcs(reinterpret_cast<const float4*>(
                          x + (size_t)(base_bs + r) * C_) + t);

    // Independent zero-fill of the same 8 output rows (overwritten later
    // only for the ~12.5% selected positions).
    const float4 z = make_float4(0.f, 0.f, 0.f, 0.f);
    #pragma unroll
    for (int r = 0; r < 8; r++)
        __stcs(reinterpret_cast<float4*>(
                   out + (size_t)(base_bs + r) * C_) + t, z);

    #pragma unroll
    for (int r = 0; r < 8; r++) {
        float ss = v[r].x * v[r].x + v[r].y * v[r].y
                 + v[r].z * v[r].z + v[r].w * v[r].w;
        #pragma unroll
        for (int off = 8; off > 0; off >>= 1)
            ss += __shfl_down_sync(0xffffffffu, ss, off, 16);
        if ((t & 15) == 0) {
            const int bs = base_bs + r;
            const int b  = bs >> 11;
            const int s  = bs & (S_ - 1);
            g_norms[((b << 4) + (t >> 4)) * S_ + s] = ss;
        }
    }
}

// ---------------------------------------------------------------------------
// K2: exact Kth-largest per row via 4-pass radix select on the monotone uint
// encoding (values >= 0). Per-warp replicated histograms (8 copies) because
// pass 0 concentrates nearly all values into 1-2 bins (clustered exponents),
// which would serialize same-address smem atomics. 512 blocks x 256 thr.
// ---------------------------------------------------------------------------
__global__ __launch_bounds__(256) void k_select() {
    __shared__ unsigned int vals[S_];
    __shared__ int hist[8][256];
    __shared__ int sh_k;
    __shared__ unsigned int sh_prefix;
    __shared__ int n_gt, eq_cnt;

    const int row = blockIdx.x;
    const int tid = threadIdx.x;
    const int w   = tid >> 5;               // warp id 0..7
    const float* nr = g_norms + (size_t)row * S_;

    #pragma unroll
    for (int i = tid; i < S_; i += 256)
        vals[i] = __float_as_uint(nr[i]);
    if (tid == 0) { sh_k = K_; sh_prefix = 0u; n_gt = 0; eq_cnt = 0; }
    #pragma unroll
    for (int c = 0; c < 8; c++) hist[c][tid] = 0;
    __syncthreads();

    int k = K_;
    unsigned int prefix = 0u;
    #pragma unroll
    for (int shift = 24; shift >= 0; shift -= 8) {
        if (shift == 24) {
            #pragma unroll
            for (int i = tid; i < S_; i += 256)
                atomicAdd(&hist[w][vals[i] >> 24], 1);
        } else {
            const unsigned int pmask = 0xFFFFFFFFu << (shift + 8);
            #pragma unroll
            for (int i = tid; i < S_; i += 256) {
                const unsigned int u = vals[i];
                if ((u & pmask) == prefix)
                    atomicAdd(&hist[w][(u >> shift) & 255], 1);
            }
        }
        __syncthreads();

        if (tid < 32) {
            const int binbase = 255 - tid * 8;  // lane 0 owns top bins
            int bc[8];
            int c = 0;
            #pragma unroll
            for (int j = 0; j < 8; j++) {
                int h = 0;
                #pragma unroll
                for (int cp = 0; cp < 8; cp++) h += hist[cp][binbase - j];
                bc[j] = h;
                c += h;
            }
            int inc = c;
            #pragma unroll
            for (int off = 1; off < 32; off <<= 1) {
                const int nth = __shfl_up_sync(0xffffffffu, inc, off);
                if (tid >= off) inc += nth;
            }
            const int pre = inc - c;
            const bool hit = (pre < k) && (pre + c >= k);
            const unsigned int bal = __ballot_sync(0xffffffffu, hit);
            if (tid == (__ffs(bal) - 1)) {
                int cum = pre;
                #pragma unroll
                for (int j = 0; j < 8; j++) {
                    if (cum + bc[j] >= k) {
                        sh_k = k - cum;
                        sh_prefix = prefix |
                            ((unsigned int)(binbase - j) << shift);
                        break;
                    }
                    cum += bc[j];
                }
            }
        }
        __syncthreads();
        k = sh_k;
        prefix = sh_prefix;
        #pragma unroll
        for (int c = 0; c < 8; c++) hist[c][tid] = 0;
        __syncthreads();
    }

    const float thr = __uint_as_float(prefix);  // exact Kth largest

    int loc = 0;
    #pragma unroll
    for (int i = tid; i < S_; i += 256)
        loc += (__uint_as_float(vals[i]) > thr) ? 1 : 0;
    #pragma unroll
    for (int off = 16; off > 0; off >>= 1)
        loc += __shfl_down_sync(0xffffffffu, loc, off);
    if ((tid & 31) == 0) atomicAdd(&n_gt, loc);
    __syncthreads();

    const int ngt = n_gt;
    unsigned char* mrow = g_mask + (size_t)row * S_;
    #pragma unroll
    for (int i = tid; i < S_; i += 256) {
        const float v = __uint_as_float(vals[i]);
        unsigned char m = 0;
        if (v > thr) m = 1;
        else if (v == thr) {
            const int p = atomicAdd(&eq_cnt, 1);
            m = (ngt + p < K_) ? 1 : 0;
        }
        mrow[i] = m;
    }
}

// ---------------------------------------------------------------------------
// K3: selected-only copy. Zeros already written by K1. One uint64 mask load
// covers 8 rows for this thread's group; ~12.5% of rows get copied.
// Traffic: ~1MB mask + ~32MB read + ~32MB write.
// ---------------------------------------------------------------------------
__global__ __launch_bounds__(256) void k_apply_sel(const float* __restrict__ x,
                                                   float* __restrict__ out) {
    const int base_bs = blockIdx.x << 3;   // aligned to 8; same b for all 8
    const int t  = threadIdx.x;
    const int g  = t >> 4;
    const int b  = base_bs >> 11;
    const int s0 = base_bs & (S_ - 1);

    const unsigned long long mbits =
        *reinterpret_cast<const unsigned long long*>(
            &g_mask[(size_t)((b << 4) + g) * S_ + s0]);
    if (mbits == 0ull) return;

    float4 v[8];
    #pragma unroll
    for (int r = 0; r < 8; r++) {
        if ((mbits >> (r << 3)) & 0xFFull)
            v[r] = __ldcs(reinterpret_cast<const float4*>(
                              x + (size_t)(base_bs + r) * C_) + t);
    }
    #pragma unroll
    for (int r = 0; r < 8; r++) {
        if ((mbits >> (r << 3)) & 0xFFull)
            reinterpret_cast<float4*>(
                out + (size_t)(base_bs + r) * C_)[t] = v[r];
    }
}

extern "C" void kernel_launch(void* const* d_in, const int* in_sizes, int n_in,
                              void* d_out, int out_size) {
    const float* x = (const float*)d_in[0];
    float* out = (float*)d_out;
    k_norms_zero<<<(B_ * S_) / 8, 256>>>(x, out);
    k_select    <<<B_ * G_, 256>>>();
    k_apply_sel <<<(B_ * S_) / 8, 256>>>(x, out);
}

// round 7
// speedup vs baseline: 1.0571x; 1.0368x over previous
#include <cuda_runtime.h>
#include <cstdint>

#define B_  32
#define S_  2048
#define C_  1024
#define G_  16
#define K_  256

__device__ float g_norms[B_ * G_ * S_];   // (B*g, S) row-major

// ---------------------------------------------------------------------------
// K1 (fused): sum-of-squares per (b,s,group) AND zero-fill of out.
// 8 bs-rows per block, 256 threads; loads and zero-stores are independent,
// so read and write streams overlap (measured 6.26 TB/s aggregate).
// ---------------------------------------------------------------------------
__global__ __launch_bounds__(256) void k_norms_zero(const float* __restrict__ x,
                                                    float* __restrict__ out) {
    const int base_bs = blockIdx.x << 3;
    const int t = threadIdx.x;

    float4 v[8];
    #pragma unroll
    for (int r = 0; r < 8; r++)
        v[r] = __ldcs(reinterpret_cast<const float4*>(
                          x + (size_t)(base_bs + r) * C_) + t);

    const float4 z = make_float4(0.f, 0.f, 0.f, 0.f);
    #pragma unroll
    for (int r = 0; r < 8; r++)
        __stcs(reinterpret_cast<float4*>(
                   out + (size_t)(base_bs + r) * C_) + t, z);

    #pragma unroll
    for (int r = 0; r < 8; r++) {
        float ss = v[r].x * v[r].x + v[r].y * v[r].y
                 + v[r].z * v[r].z + v[r].w * v[r].w;
        #pragma unroll
        for (int off = 8; off > 0; off >>= 1)
            ss += __shfl_down_sync(0xffffffffu, ss, off, 16);
        if ((t & 15) == 0) {
            const int bs = base_bs + r;
            const int b  = bs >> 11;
            const int s  = bs & (S_ - 1);
            g_norms[((b << 4) + (t >> 4)) * S_ + s] = ss;
        }
    }
}

// ---------------------------------------------------------------------------
// K2 (fused select + apply): per (b,g) row, 4-pass radix select for the exact
// Kth-largest (monotone uint encoding; per-warp replicated histograms to
// dodge same-bin atomic serialization), build the 256 selected indices in
// smem with exact-K tie fill, then directly copy the selected 64-channel
// chunks x -> out. No gmem mask, no third kernel.
// ---------------------------------------------------------------------------
__global__ __launch_bounds__(256) void k_select_apply(const float* __restrict__ x,
                                                      float* __restrict__ out) {
    __shared__ unsigned int vals[S_];
    __shared__ int hist[8][256];
    __shared__ int sh_k;
    __shared__ unsigned int sh_prefix;
    __shared__ int nsel;
    __shared__ unsigned short sel[K_];

    const int row = blockIdx.x;             // b*16 + g
    const int b   = row >> 4;
    const int g   = row & 15;
    const int tid = threadIdx.x;
    const int w   = tid >> 5;
    const float* nr = g_norms + (size_t)row * S_;

    #pragma unroll
    for (int i = tid; i < S_; i += 256)
        vals[i] = __float_as_uint(nr[i]);
    if (tid == 0) { sh_k = K_; sh_prefix = 0u; nsel = 0; }
    #pragma unroll
    for (int c = 0; c < 8; c++) hist[c][tid] = 0;
    __syncthreads();

    int k = K_;
    unsigned int prefix = 0u;
    #pragma unroll
    for (int shift = 24; shift >= 0; shift -= 8) {
        if (shift == 24) {
            #pragma unroll
            for (int i = tid; i < S_; i += 256)
                atomicAdd(&hist[w][vals[i] >> 24], 1);
        } else {
            const unsigned int pmask = 0xFFFFFFFFu << (shift + 8);
            #pragma unroll
            for (int i = tid; i < S_; i += 256) {
                const unsigned int u = vals[i];
                if ((u & pmask) == prefix)
                    atomicAdd(&hist[w][(u >> shift) & 255], 1);
            }
        }
        __syncthreads();

        if (tid < 32) {
            const int binbase = 255 - tid * 8;  // lane 0 owns top bins
            int bc[8];
            int c = 0;
            #pragma unroll
            for (int j = 0; j < 8; j++) {
                int h = 0;
                #pragma unroll
                for (int cp = 0; cp < 8; cp++) h += hist[cp][binbase - j];
                bc[j] = h;
                c += h;
            }
            int inc = c;
            #pragma unroll
            for (int off = 1; off < 32; off <<= 1) {
                const int nth = __shfl_up_sync(0xffffffffu, inc, off);
                if (tid >= off) inc += nth;
            }
            const int pre = inc - c;
            const bool hit = (pre < k) && (pre + c >= k);
            const unsigned int bal = __ballot_sync(0xffffffffu, hit);
            if (tid == (__ffs(bal) - 1)) {
                int cum = pre;
                #pragma unroll
                for (int j = 0; j < 8; j++) {
                    if (cum + bc[j] >= k) {
                        sh_k = k - cum;
                        sh_prefix = prefix |
                            ((unsigned int)(binbase - j) << shift);
                        break;
                    }
                    cum += bc[j];
                }
            }
        }
        __syncthreads();
        k = sh_k;
        prefix = sh_prefix;
        if (shift > 0) {
            #pragma unroll
            for (int c = 0; c < 8; c++) hist[c][tid] = 0;
            __syncthreads();
        }
    }

    const float thr = __uint_as_float(prefix);  // exact Kth largest

    // Phase 1: append all strictly-greater indices.
    #pragma unroll
    for (int i = tid; i < S_; i += 256) {
        if (__uint_as_float(vals[i]) > thr) {
            const int p = atomicAdd(&nsel, 1);
            sel[p] = (unsigned short)i;
        }
    }
    __syncthreads();
    // Phase 2: fill remaining slots with ties (first-come; exact K total).
    #pragma unroll
    for (int i = tid; i < S_; i += 256) {
        if (__uint_as_float(vals[i]) == thr) {
            const int p = atomicAdd(&nsel, 1);
            if (p < K_) sel[p] = (unsigned short)i;
        }
    }
    __syncthreads();

    // Copy phase: 16 subgroups of 16 lanes; each lane moves one float4 of a
    // selected 64-channel chunk; 16 positions per iteration, batched 8-deep.
    const int sub  = tid >> 4;   // 0..15: which selected slot in this iter
    const int lane = tid & 15;   // 0..15: which float4 within the chunk
    const float* xb = x   + (size_t)b * S_ * C_ + g * 64;
    float*       ob = out + (size_t)b * S_ * C_ + g * 64;

    #pragma unroll
    for (int half = 0; half < 2; half++) {
        int si[8];
        float4 v[8];
        #pragma unroll
        for (int it = 0; it < 8; it++)
            si[it] = sel[(half * 8 + it) * 16 + sub];
        #pragma unroll
        for (int it = 0; it < 8; it++)
            v[it] = __ldcs(reinterpret_cast<const float4*>(
                               xb + (size_t)si[it] * C_) + lane);
        #pragma unroll
        for (int it = 0; it < 8; it++)
            reinterpret_cast<float4*>(ob + (size_t)si[it] * C_)[lane] = v[it];
    }
}

extern "C" void kernel_launch(void* const* d_in, const int* in_sizes, int n_in,
                              void* d_out, int out_size) {
    const float* x = (const float*)d_in[0];
    float* out = (float*)d_out;
    k_norms_zero  <<<(B_ * S_) / 8, 256>>>(x, out);
    k_select_apply<<<B_ * G_, 256>>>(x, out);
}